// round 4
// baseline (speedup 1.0000x reference)
#include <cuda_runtime.h>

// ShadingLayer: out[b,c,h,w] = sum_k L[b,c,k] * H_k(n[b,:,h,w])
// R3: 4 float4-groups/thread, 12 front-batched LDG.128 (MLP=12),
// block-shared folded coefficients, streaming hints.
//
// d_in[0]: recnormalch fp32 (64,3,512,512)
// d_in[1]: fc_light    fp32 (64,27)
// d_out  : fp32 (64,3,512,512)

#define C1f 0.8862269254527580f
#define C2f 1.0233267079464885f
#define C3f 0.2477079561003757f
#define C4f 0.8580855308097834f
#define C5f 0.4290427654048917f

static __device__ __forceinline__ float4 ldcs4(const float* p) {
    return __ldcs(reinterpret_cast<const float4*>(p));
}
static __device__ __forceinline__ void stcs4(float* p, float4 v) {
    __stcs(reinterpret_cast<float4*>(p), v);
}

__global__ __launch_bounds__(256)
void shading_kernel(const float* __restrict__ nrm,
                    const float* __restrict__ light,
                    float* __restrict__ out) {
    constexpr int HW = 512 * 512;          // pixels per plane
    // 65536 float4-groups/plane; 1024 groups per block -> 64 blocks/batch
    const unsigned bid = blockIdx.x;
    const int b   = bid >> 6;              // batch
    const int blk = bid & 63;              // block within batch
    const int v0  = blk * 1024 + threadIdx.x;  // first float4-group

    // ---- block-cooperative coefficient load + fold ----
    __shared__ float sa[27];               // folded a[c][k], c-major
    if (threadIdx.x < 27) {
        const int c = threadIdx.x / 9;
        const int k = threadIdx.x - 9 * c;
        // fold SH constant into light coefficient
        const float ck = (k == 0) ? C1f
                       : (k <= 3) ? C2f
                       : (k == 4) ? C3f
                       : (k == 7) ? C5f
                       : C4f;              // k = 5,6,8
        sa[threadIdx.x] = ck * __ldg(light + b * 27 + threadIdx.x);
    }

    // ---- front-batch all 12 data loads (MLP=12) ----
    const float* p = nrm + (size_t)b * 3 * HW + (size_t)v0 * 4;
    float4 X[4], Y[4], Z[4];
    #pragma unroll
    for (int g = 0; g < 4; g++) {
        X[g] = ldcs4(p);
        Y[g] = ldcs4(p + HW);
        Z[g] = ldcs4(p + 2 * HW);
        p += 1024;                         // +256 groups * 4 floats
    }

    __syncthreads();
    float a[3][9];
    #pragma unroll
    for (int c = 0; c < 3; c++)
        #pragma unroll
        for (int k = 0; k < 9; k++)
            a[c][k] = sa[9 * c + k];

    float* q = out + (size_t)b * 3 * HW + (size_t)v0 * 4;

    #pragma unroll
    for (int g = 0; g < 4; g++) {
        const float xs[4] = {X[g].x, X[g].y, X[g].z, X[g].w};
        const float ys[4] = {Y[g].x, Y[g].y, Y[g].z, Y[g].w};
        const float zs[4] = {Z[g].x, Z[g].y, Z[g].z, Z[g].w};
        float o[3][4];

        #pragma unroll
        for (int j = 0; j < 4; j++) {
            const float x = xs[j], y = ys[j], z = zs[j];
            const float xx = x * x;
            const float yy = y * y;
            const float b5 = 2.0f * z * z - xx - yy;
            const float b6 = x * z;
            const float b7 = y * z;
            const float b8 = xx - yy;
            const float b9 = x * y;
            #pragma unroll
            for (int c = 0; c < 3; c++) {
                float r = a[c][0];
                r = fmaf(a[c][1], z,  r);
                r = fmaf(a[c][2], x,  r);
                r = fmaf(a[c][3], y,  r);
                r = fmaf(a[c][4], b5, r);
                r = fmaf(a[c][5], b6, r);
                r = fmaf(a[c][6], b7, r);
                r = fmaf(a[c][7], b8, r);
                r = fmaf(a[c][8], b9, r);
                o[c][j] = r;
            }
        }

        stcs4(q,          make_float4(o[0][0], o[0][1], o[0][2], o[0][3]));
        stcs4(q + HW,     make_float4(o[1][0], o[1][1], o[1][2], o[1][3]));
        stcs4(q + 2 * HW, make_float4(o[2][0], o[2][1], o[2][2], o[2][3]));
        q += 1024;
    }
}

extern "C" void kernel_launch(void* const* d_in, const int* in_sizes, int n_in,
                              void* d_out, int out_size) {
    const float* nrm   = (const float*)d_in[0];
    const float* light = (const float*)d_in[1];
    float* out = (float*)d_out;

    // 64 batches * 64 blocks = 4096 blocks, 256 threads, 4 groups/thread
    shading_kernel<<<4096, 256>>>(nrm, light, out);
}